// round 1
// baseline (speedup 1.0000x reference)
#include <cuda_runtime.h>

// Fused 3D windowed attention block.
//   x:      (1, 128, 30, 62, 126) f32
//   qkv_w:  (384, 128), qkv_b: (384,)
//   conv_w: (128, 128), conv_b: (128,)
//   out:    (1, 128, 30, 62, 126) f32
//
// One CTA per 4x4x4 window (nW = 8*16*32 = 4096). Phases (SMEM-resident):
//   1) gather window x -> xs[64][132]
//   2) qkv = xs @ qkv_w^T + b  -> qs[64][388]   (3 chunks of 128 cols)
//   3) per-head softmax attention (streaming, no max-sub; pad-mask = hard zero)
//      -> y_s[64][132] (reuses xs region)
//   4) out_tile = y_s @ conv_w^T + conv_b -> scattered store to out (cropped)

#define D0 30
#define H0 62
#define W0 126
#define MTOT (30*62*126)   // 234360 voxels

// SMEM float offsets
#define XS_OFF 0            // [64][132]  = 8448 floats (reused as y_s)
#define QS_OFF 8448         // [64][388]  = 24832 floats
#define WT_OFF (8448+24832) // [128][132] = 16896 floats
#define SMEM_FLOATS (8448+24832+16896)  // 50176 floats = 200704 bytes

__device__ __forceinline__ float dot4(float4 a, float4 b) {
    return fmaf(a.x, b.x, fmaf(a.y, b.y, fmaf(a.z, b.z, a.w * b.w)));
}

__global__ void __launch_bounds__(256, 1)
fused_window_attn_kernel(const float* __restrict__ x,
                         const float* __restrict__ qkv_w,
                         const float* __restrict__ qkv_b,
                         const float* __restrict__ conv_w,
                         const float* __restrict__ conv_b,
                         float* __restrict__ out)
{
    extern __shared__ float sm[];
    float* xs = sm + XS_OFF;   // [64][132] window input, later y_s
    float* qs = sm + QS_OFF;   // [64][388] qkv
    float* wt = sm + WT_OFF;   // [128][132] weight tile

    const int t  = threadIdx.x;
    const int wi = blockIdx.x;
    const int bz = wi >> 9;
    const int by = (wi >> 5) & 15;
    const int bx = wi & 31;
    const int z0 = bz * 4, y0 = by * 4, x0 = bx * 4;

    // ---------------- phase 1: gather window ----------------
    for (int idx = t; idx < 64 * 128; idx += 256) {
        int l = idx & 63;
        int c = idx >> 6;
        int gz = z0 + (l >> 4);
        int gy = y0 + ((l >> 2) & 3);
        int gx = x0 + (l & 3);
        float v = 0.f;
        if (gz < D0 && gy < H0 && gx < W0)
            v = x[((c * D0 + gz) * H0 + gy) * W0 + gx];
        xs[l * 132 + c] = v;
    }

    const int tx = t & 15;    // col group
    const int ty = t >> 4;    // row group

    // ---------------- phase 2: QKV GEMM (64 x 384 x 128) ----------------
    for (int chunk = 0; chunk < 3; ++chunk) {
        __syncthreads();  // xs ready (chunk 0) / previous chunk compute done
        for (int idx = t; idx < 128 * 128; idx += 256) {
            int o = idx >> 7, c = idx & 127;
            wt[o * 132 + c] = qkv_w[(chunk * 128 + o) * 128 + c];
        }
        __syncthreads();

        float acc[4][8];
        #pragma unroll
        for (int i = 0; i < 4; ++i)
            #pragma unroll
            for (int j = 0; j < 8; ++j) acc[i][j] = 0.f;

        #pragma unroll 8
        for (int k = 0; k < 128; ++k) {
            float a[4], b[8];
            #pragma unroll
            for (int i = 0; i < 4; ++i) a[i] = xs[(ty + 16 * i) * 132 + k];
            #pragma unroll
            for (int j = 0; j < 8; ++j) b[j] = wt[(tx + 16 * j) * 132 + k];
            #pragma unroll
            for (int i = 0; i < 4; ++i)
                #pragma unroll
                for (int j = 0; j < 8; ++j)
                    acc[i][j] = fmaf(a[i], b[j], acc[i][j]);
        }

        #pragma unroll
        for (int i = 0; i < 4; ++i) {
            int l = ty + 16 * i;
            #pragma unroll
            for (int j = 0; j < 8; ++j) {
                int n = chunk * 128 + tx + 16 * j;
                qs[l * 388 + n] = acc[i][j] + qkv_b[n];
            }
        }
    }
    __syncthreads();

    // ---------------- phase 3: attention ----------------
    // pad bitmask over the 64 window positions
    unsigned long long pm = 0ull;
    if (bz == 7 || by == 15 || bx == 31) {
        #pragma unroll
        for (int m = 0; m < 64; ++m) {
            bool p = (bz == 7 && (m >> 4) >= 2) ||
                     (by == 15 && ((m >> 2) & 3) >= 2) ||
                     (bx == 31 && (m & 3) >= 2);
            pm |= (unsigned long long)(p ? 1u : 0u) << m;
        }
    }

    const int head = t >> 5;   // warp == head
    const int lane = t & 31;
    const int r0 = lane, r1 = lane + 32;

    const float* qp0 = qs + r0 * 388 + head * 16;
    const float* qp1 = qs + r1 * 388 + head * 16;
    float4 q0[4], q1[4];
    #pragma unroll
    for (int i = 0; i < 4; ++i) {
        q0[i] = *(const float4*)(qp0 + 4 * i);
        q1[i] = *(const float4*)(qp1 + 4 * i);
    }

    float4 a0[4], a1[4];
    #pragma unroll
    for (int i = 0; i < 4; ++i) {
        a0[i] = make_float4(0.f, 0.f, 0.f, 0.f);
        a1[i] = make_float4(0.f, 0.f, 0.f, 0.f);
    }
    float sum0 = 0.f, sum1 = 0.f;
    const unsigned p0 = (unsigned)(pm >> r0) & 1u;
    const unsigned p1 = (unsigned)(pm >> r1) & 1u;

    const float* kbase = qs + 128 + head * 16;
    const float* vbase = qs + 256 + head * 16;

    #pragma unroll 2
    for (int m = 0; m < 64; ++m) {
        const float* kp = kbase + m * 388;
        float4 k0 = *(const float4*)(kp + 0);
        float4 k1 = *(const float4*)(kp + 4);
        float4 k2 = *(const float4*)(kp + 8);
        float4 k3 = *(const float4*)(kp + 12);

        float s0 = dot4(q0[0], k0) + dot4(q0[1], k1) + dot4(q0[2], k2) + dot4(q0[3], k3);
        float s1 = dot4(q1[0], k0) + dot4(q1[1], k1) + dot4(q1[2], k2) + dot4(q1[3], k3);
        s0 *= 0.25f;
        s1 *= 0.25f;

        // scores are bounded (|s| < ~10) so exp without max-subtraction is safe;
        // mask pairs with differing pad flags to exactly 0 (== exp(-1000) in fp32)
        unsigned pmm = (unsigned)(pm >> m) & 1u;
        float e0 = (pmm == p0) ? __expf(s0) : 0.f;
        float e1 = (pmm == p1) ? __expf(s1) : 0.f;
        sum0 += e0;
        sum1 += e1;

        const float* vp = vbase + m * 388;
        float4 v0 = *(const float4*)(vp + 0);
        float4 v1 = *(const float4*)(vp + 4);
        float4 v2 = *(const float4*)(vp + 8);
        float4 v3 = *(const float4*)(vp + 12);

        a0[0].x = fmaf(e0, v0.x, a0[0].x); a0[0].y = fmaf(e0, v0.y, a0[0].y);
        a0[0].z = fmaf(e0, v0.z, a0[0].z); a0[0].w = fmaf(e0, v0.w, a0[0].w);
        a0[1].x = fmaf(e0, v1.x, a0[1].x); a0[1].y = fmaf(e0, v1.y, a0[1].y);
        a0[1].z = fmaf(e0, v1.z, a0[1].z); a0[1].w = fmaf(e0, v1.w, a0[1].w);
        a0[2].x = fmaf(e0, v2.x, a0[2].x); a0[2].y = fmaf(e0, v2.y, a0[2].y);
        a0[2].z = fmaf(e0, v2.z, a0[2].z); a0[2].w = fmaf(e0, v2.w, a0[2].w);
        a0[3].x = fmaf(e0, v3.x, a0[3].x); a0[3].y = fmaf(e0, v3.y, a0[3].y);
        a0[3].z = fmaf(e0, v3.z, a0[3].z); a0[3].w = fmaf(e0, v3.w, a0[3].w);

        a1[0].x = fmaf(e1, v0.x, a1[0].x); a1[0].y = fmaf(e1, v0.y, a1[0].y);
        a1[0].z = fmaf(e1, v0.z, a1[0].z); a1[0].w = fmaf(e1, v0.w, a1[0].w);
        a1[1].x = fmaf(e1, v1.x, a1[1].x); a1[1].y = fmaf(e1, v1.y, a1[1].y);
        a1[1].z = fmaf(e1, v1.z, a1[1].z); a1[1].w = fmaf(e1, v1.w, a1[1].w);
        a1[2].x = fmaf(e1, v2.x, a1[2].x); a1[2].y = fmaf(e1, v2.y, a1[2].y);
        a1[2].z = fmaf(e1, v2.z, a1[2].z); a1[2].w = fmaf(e1, v2.w, a1[2].w);
        a1[3].x = fmaf(e1, v3.x, a1[3].x); a1[3].y = fmaf(e1, v3.y, a1[3].y);
        a1[3].z = fmaf(e1, v3.z, a1[3].z); a1[3].w = fmaf(e1, v3.w, a1[3].w);
    }

    float inv0 = 1.0f / sum0;
    float inv1 = 1.0f / sum1;

    // write attention output into y_s (reuses xs region; xs is dead after phase 2)
    float* yrow0 = xs + r0 * 132 + head * 16;
    float* yrow1 = xs + r1 * 132 + head * 16;
    #pragma unroll
    for (int i = 0; i < 4; ++i) {
        float4 o0 = make_float4(a0[i].x * inv0, a0[i].y * inv0, a0[i].z * inv0, a0[i].w * inv0);
        float4 o1 = make_float4(a1[i].x * inv1, a1[i].y * inv1, a1[i].z * inv1, a1[i].w * inv1);
        *(float4*)(yrow0 + 4 * i) = o0;
        *(float4*)(yrow1 + 4 * i) = o1;
    }
    __syncthreads();

    // ---------------- phase 4: 1x1 conv GEMM (64 x 128 x 128) ----------------
    for (int idx = t; idx < 128 * 128; idx += 256) {
        int o = idx >> 7, c = idx & 127;
        wt[o * 132 + c] = conv_w[o * 128 + c];
    }
    __syncthreads();

    float cacc[8][4];
    #pragma unroll
    for (int i = 0; i < 8; ++i)
        #pragma unroll
        for (int j = 0; j < 4; ++j) cacc[i][j] = 0.f;

    #pragma unroll 8
    for (int k = 0; k < 128; ++k) {
        float a[8], b[4];
        #pragma unroll
        for (int i = 0; i < 8; ++i) a[i] = wt[(ty + 16 * i) * 132 + k];   // o rows
        #pragma unroll
        for (int j = 0; j < 4; ++j) b[j] = xs[(tx + 16 * j) * 132 + k];   // voxel rows (y_s)
        #pragma unroll
        for (int i = 0; i < 8; ++i)
            #pragma unroll
            for (int j = 0; j < 4; ++j)
                cacc[i][j] = fmaf(a[i], b[j], cacc[i][j]);
    }

    #pragma unroll
    for (int j = 0; j < 4; ++j) {
        int m  = tx + 16 * j;
        int gz = z0 + (m >> 4);
        int gy = y0 + ((m >> 2) & 3);
        int gx = x0 + (m & 3);
        if (gz < D0 && gy < H0 && gx < W0) {
            size_t vaddr = (size_t)(gz * H0 + gy) * W0 + gx;
            #pragma unroll
            for (int i = 0; i < 8; ++i) {
                int o = ty + 16 * i;
                out[(size_t)o * MTOT + vaddr] = cacc[i][j] + conv_b[o];
            }
        }
    }
}

extern "C" void kernel_launch(void* const* d_in, const int* in_sizes, int n_in,
                              void* d_out, int out_size)
{
    const float* x      = (const float*)d_in[0];
    const float* qkv_w  = (const float*)d_in[1];
    const float* qkv_b  = (const float*)d_in[2];
    const float* conv_w = (const float*)d_in[3];
    const float* conv_b = (const float*)d_in[4];
    float* out = (float*)d_out;

    cudaFuncSetAttribute(fused_window_attn_kernel,
                         cudaFuncAttributeMaxDynamicSharedMemorySize,
                         SMEM_FLOATS * (int)sizeof(float));

    fused_window_attn_kernel<<<4096, 256, SMEM_FLOATS * sizeof(float)>>>(
        x, qkv_w, qkv_b, conv_w, conv_b, out);
}